// round 6
// baseline (speedup 1.0000x reference)
#include <cuda_runtime.h>
#include <cuda_bf16.h>
#include <math.h>
#include <stdint.h>

// ---------------- problem constants ----------------
#define B_   32
#define LQ   64
#define LK   256
#define D_   128
#define NN   32
#define NC   33          // 1 pos + 32 negs
#define TINV 20.0f

// per-(b,candidate) logit (pre-temperature)
__device__ float g_logits[B_ * NC];

// ---------------- smem layout (bytes) ----------------
// padded rows: 128 bf16 = 256B data + 16B pad = 272B stride (conflict-free ldmatrix)
#define ROWB    272
#define SM_INVK 0                        // 2 x 32 floats (double-buffered K norms)
#define SM_INVQ 512                      // 64 floats
#define SM_RED  768                      // 128 floats
#define SM_QHI  2048                     // 64 rows x 272B
#define SM_QLO  (SM_QHI + 64 * ROWB)     // 19456
#define SM_K0HI (SM_QLO + 64 * ROWB)     // 36864  (chunk buffer 0, 32 rows)
#define SM_K0LO (SM_K0HI + 32 * ROWB)    // 45568
#define SM_K1HI (SM_K0LO + 32 * ROWB)    // 54272  (chunk buffer 1)
#define SM_K1LO (SM_K1HI + 32 * ROWB)    // 62976
#define SM_BYTES (SM_K1LO + 32 * ROWB)   // 71680
#define DLO_Q   (64 * ROWB)              // Q hi->lo offset
#define DLO_K   (32 * ROWB)              // K hi->lo offset

static __device__ __forceinline__ uint32_t smem_u32(const void* p) {
    uint32_t a;
    asm("{ .reg .u64 t; cvta.to.shared.u64 t, %1; cvt.u32.u64 %0, t; }" : "=r"(a) : "l"(p));
    return a;
}

#define LDSM_X4(r0, r1, r2, r3, a) \
    asm volatile("ldmatrix.sync.aligned.m8n8.x4.shared.b16 {%0,%1,%2,%3}, [%4];" \
                 : "=r"(r0), "=r"(r1), "=r"(r2), "=r"(r3) : "r"(a))

#define MMA16816(c, a0, a1, a2, a3, b0, b1) \
    asm volatile("mma.sync.aligned.m16n8k16.row.col.f32.bf16.bf16.f32 " \
                 "{%0,%1,%2,%3}, {%4,%5,%6,%7}, {%8,%9}, {%0,%1,%2,%3};" \
                 : "+f"((c)[0]), "+f"((c)[1]), "+f"((c)[2]), "+f"((c)[3]) \
                 : "r"(a0), "r"(a1), "r"(a2), "r"(a3), "r"(b0), "r"(b1))

// split (x,y) into packed bf16 hi and lo pairs
static __device__ __forceinline__ void cvt2(float x, float y, uint32_t& hi, uint32_t& lo) {
    __nv_bfloat16 hx = __float2bfloat16_rn(x);
    __nv_bfloat16 hy = __float2bfloat16_rn(y);
    __nv_bfloat16 lx = __float2bfloat16_rn(x - __bfloat162float(hx));
    __nv_bfloat16 ly = __float2bfloat16_rn(y - __bfloat162float(hy));
    hi = (uint32_t)__bfloat16_as_ushort(hx) | ((uint32_t)__bfloat16_as_ushort(hy) << 16);
    lo = (uint32_t)__bfloat16_as_ushort(lx) | ((uint32_t)__bfloat16_as_ushort(ly) << 16);
}

// convert one float4 (cols lane*4..+3 of `row`) and store hi/lo into padded smem
static __device__ __forceinline__ void cvtstore(float4 v, char* hi_base, char* lo_base,
                                                int row, int lane) {
    uint32_t ha, la, hb, lb;
    cvt2(v.x, v.y, ha, la);
    cvt2(v.z, v.w, hb, lb);
    const uint32_t off = (uint32_t)row * ROWB + (uint32_t)lane * 8;
    *(uint2*)(hi_base + off) = make_uint2(ha, hb);
    *(uint2*)(lo_base + off) = make_uint2(la, lb);
}

static __device__ __forceinline__ float ssq4(float4 v) {
    return v.x * v.x + v.y * v.y + v.z * v.z + v.w * v.w;
}

__global__ __launch_bounds__(256, 2)
void maxsim_scores_kernel(const float* __restrict__ query,
                          const float* __restrict__ pos_key,
                          const float* __restrict__ neg_key)
{
    extern __shared__ __align__(1024) char smc[];
    const uint32_t sb = smem_u32(smc);
    float* invk = (float*)(smc + SM_INVK);   // [2][32]
    float* invq = (float*)(smc + SM_INVQ);   // [64]
    float* red  = (float*)(smc + SM_RED);    // [128]

    const int cj = blockIdx.x;          // b*NC + j
    const int b  = cj / NC;
    const int j  = cj % NC;

    const float* qptr = query + (size_t)b * LQ * D_;
    const float* kptr = (j == 0)
        ? (pos_key + (size_t)b * LK * D_)
        : (neg_key + ((size_t)(b * NN + (j - 1))) * LK * D_);

    const int tid  = threadIdx.x;
    const int wid  = tid >> 5;
    const int lane = tid & 31;
    const int qt   = wid & 3;           // q tile: rows qt*16..qt*16+15
    const int kh   = wid >> 2;          // key half within 32-chunk: keys kh*16..+15

    // ---- Prologue: Q load+cvt (+invq), K chunk 0 (32 rows) load+cvt (+invk[0]) ----
    #pragma unroll
    for (int i = 0; i < 8; i++) {
        const int row = wid + 8 * i;
        float4 v = ((const float4*)(qptr + (size_t)row * D_))[lane];
        cvtstore(v, smc + SM_QHI, smc + SM_QLO, row, lane);
        float ss = ssq4(v);
        #pragma unroll
        for (int o = 16; o > 0; o >>= 1) ss += __shfl_xor_sync(0xffffffffu, ss, o);
        if (lane == 0) invq[row] = 1.0f / fmaxf(sqrtf(ss), 1e-12f);
    }
    #pragma unroll
    for (int i = 0; i < 4; i++) {
        const int row = wid + 8 * i;
        float4 v = ((const float4*)(kptr + (size_t)row * D_))[lane];
        cvtstore(v, smc + SM_K0HI, smc + SM_K0LO, row, lane);
        float ss = ssq4(v);
        #pragma unroll
        for (int o = 16; o > 0; o >>= 1) ss += __shfl_xor_sync(0xffffffffu, ss, o);
        if (lane == 0) invk[row] = 1.0f / fmaxf(sqrtf(ss), 1e-12f);
    }
    __syncthreads();

    // ldmatrix base addresses
    const uint32_t addrA = sb + SM_QHI + (uint32_t)(qt * 16 + (lane & 15)) * ROWB
                              + (uint32_t)(16 * (lane >> 4));
    const uint32_t bcom = (uint32_t)(kh * 16 + (lane & 7) + 8 * (lane >> 4)) * ROWB
                        + (uint32_t)(16 * ((lane >> 3) & 1));
    const uint32_t addrB0 = sb + SM_K0HI + bcom;
    const uint32_t addrB1 = sb + SM_K1HI + bcom;

    float rm0 = -INFINITY, rm1 = -INFINITY;   // running per-q-row maxima

    #pragma unroll 1
    for (int c = 0; c < 8; c++) {
        const int p = c & 1;
        const bool pf = (c < 7);

        // 1. issue prefetch LDGs for chunk c+1 (4 rows/warp)
        float4 v[4];
        if (pf) {
            const float* kc = kptr + (size_t)(c + 1) * 32 * D_;
            #pragma unroll
            for (int i = 0; i < 4; i++)
                v[i] = ((const float4*)(kc + (size_t)(wid + 8 * i) * D_))[lane];
        }

        // 2. MMA over chunk c (buffer p): 3 independent accumulator banks
        float accHH[2][4], accHL[2][4], accLH[2][4];
        #pragma unroll
        for (int nt = 0; nt < 2; nt++)
            #pragma unroll
            for (int e = 0; e < 4; e++) {
                accHH[nt][e] = 0.f; accHL[nt][e] = 0.f; accLH[nt][e] = 0.f;
            }

        const uint32_t aB0 = p ? addrB1 : addrB0;
        #pragma unroll
        for (int ks = 0; ks < 8; ks++) {
            uint32_t ah0, ah1, ah2, ah3, al0, al1, al2, al3;
            const uint32_t aA = addrA + ks * 32;
            LDSM_X4(ah0, ah1, ah2, ah3, aA);
            LDSM_X4(al0, al1, al2, al3, aA + DLO_Q);
            uint32_t bh0, bh1, bh2, bh3, bl0, bl1, bl2, bl3;
            const uint32_t aB = aB0 + ks * 32;
            LDSM_X4(bh0, bh1, bh2, bh3, aB);
            LDSM_X4(bl0, bl1, bl2, bl3, aB + DLO_K);
            // 6 MMAs, all independent (distinct accumulator tiles)
            MMA16816(accHH[0], ah0, ah1, ah2, ah3, bh0, bh1);
            MMA16816(accHL[0], ah0, ah1, ah2, ah3, bl0, bl1);
            MMA16816(accLH[0], al0, al1, al2, al3, bh0, bh1);
            MMA16816(accHH[1], ah0, ah1, ah2, ah3, bh2, bh3);
            MMA16816(accHL[1], ah0, ah1, ah2, ah3, bl2, bl3);
            MMA16816(accLH[1], al0, al1, al2, al3, bh2, bh3);
        }

        // merge banks, scale by invk (this chunk), fold into running max
        const float* ivk = invk + p * 32;
        #pragma unroll
        for (int nt = 0; nt < 2; nt++) {
            const int kk = kh * 16 + nt * 8 + 2 * (lane & 3);
            const float ik0 = ivk[kk];
            const float ik1 = ivk[kk + 1];
            const float s0 = accHH[nt][0] + accHL[nt][0] + accLH[nt][0];
            const float s1 = accHH[nt][1] + accHL[nt][1] + accLH[nt][1];
            const float s2 = accHH[nt][2] + accHL[nt][2] + accLH[nt][2];
            const float s3 = accHH[nt][3] + accHL[nt][3] + accLH[nt][3];
            rm0 = fmaxf(rm0, fmaxf(s0 * ik0, s1 * ik1));
            rm1 = fmaxf(rm1, fmaxf(s2 * ik0, s3 * ik1));
        }

        // 3. convert + store prefetched chunk into buffer p^1, compute its invk
        if (pf) {
            char* hb = smc + (p ? SM_K0HI : SM_K1HI);
            float* ivn = invk + (p ^ 1) * 32;
            #pragma unroll
            for (int i = 0; i < 4; i++) {
                const int row = wid + 8 * i;
                cvtstore(v[i], hb, hb + DLO_K, row, lane);
                float ss = ssq4(v[i]);
                #pragma unroll
                for (int o = 16; o > 0; o >>= 1) ss += __shfl_xor_sync(0xffffffffu, ss, o);
                if (lane == 0) ivn[row] = 1.0f / fmaxf(sqrtf(ss), 1e-12f);
            }
        }
        __syncthreads();
    }

    // ---- reduce: max across 4-lane column group, then across key halves ----
    #pragma unroll
    for (int o = 1; o < 4; o <<= 1) {
        rm0 = fmaxf(rm0, __shfl_xor_sync(0xffffffffu, rm0, o));
        rm1 = fmaxf(rm1, __shfl_xor_sync(0xffffffffu, rm1, o));
    }
    if ((lane & 3) == 0) {
        const int row = lane >> 2;
        red[qt * 32 + row * 2 + kh]       = rm0;
        red[qt * 32 + (row + 8) * 2 + kh] = rm1;
    }
    __syncthreads();

    // ---- per-query max * invq, block-sum -> single logit ----
    float contrib = 0.f;
    if (tid < LQ) {
        const float m = fmaxf(red[tid * 2], red[tid * 2 + 1]);
        contrib = m * invq[tid];
    }
    __syncthreads();
    if (tid < LQ) {
        #pragma unroll
        for (int o = 16; o > 0; o >>= 1)
            contrib += __shfl_xor_sync(0xffffffffu, contrib, o);
        if (lane == 0) red[wid] = contrib;   // wid 0 or 1
    }
    __syncthreads();
    if (tid == 0) g_logits[cj] = red[0] + red[1];
}

// ---- finisher: log-softmax over 33 logits per batch, mean ----
__global__ void maxsim_loss_kernel(float* __restrict__ out)
{
    const int b = threadIdx.x;   // 0..31, one warp
    float mx = -INFINITY;
    float l[NC];
    #pragma unroll
    for (int j = 0; j < NC; j++) {
        l[j] = g_logits[b * NC + j] * TINV;
        mx = fmaxf(mx, l[j]);
    }
    const float l0 = l[0];
    float se = 0.f;
    #pragma unroll
    for (int j = 0; j < NC; j++) se += expf(l[j] - mx);
    float loss = (mx + logf(se)) - l0;
    #pragma unroll
    for (int off = 16; off > 0; off >>= 1)
        loss += __shfl_xor_sync(0xffffffffu, loss, off);
    if (b == 0) out[0] = loss * (1.0f / 32.0f);
}

extern "C" void kernel_launch(void* const* d_in, const int* in_sizes, int n_in,
                              void* d_out, int out_size)
{
    const float* query   = (const float*)d_in[0];
    const float* pos_key = (const float*)d_in[2];
    const float* neg_key = (const float*)d_in[4];

    cudaFuncSetAttribute(maxsim_scores_kernel,
                         cudaFuncAttributeMaxDynamicSharedMemorySize, SM_BYTES);

    maxsim_scores_kernel<<<B_ * NC, 256, SM_BYTES>>>(query, pos_key, neg_key);
    maxsim_loss_kernel<<<1, 32>>>((float*)d_out);
}